// round 7
// baseline (speedup 1.0000x reference)
#include <cuda_runtime.h>
#include <math.h>

#define EMB     2048
#define S_LEN   2048
#define B_SZ    2
#define HEADS   16
#define HDIM    128
#define QKV_N   (3*EMB)
#define MROWS   (B_SZ*S_LEN)

__device__ float  g_qkv[25165824];          // 4096 x 6144
__device__ float  g_attn[8388608];          // 4096 x 2048
__device__ float  g_cos[S_LEN*64];
__device__ float  g_sin[S_LEN*64];
__device__ float  g_colpart[B_SZ*8*EMB];
__device__ double g_psum[128];
__device__ double g_psq[128];
__device__ int    g_window;

__global__ void rope_table_kernel() {
    int idx = blockIdx.x * blockDim.x + threadIdx.x;
    if (idx >= S_LEN * 64) return;
    int s = idx >> 6, j = idx & 63;
    double inf = exp(-((double)j) * (9.210340371976184 / 64.0));
    double sp, cp;
    sincos((double)s * inf, &sp, &cp);
    g_cos[idx] = (float)cp;
    g_sin[idx] = (float)sp;
}

__global__ void stats_kernel(const float* __restrict__ x) {
    __shared__ double sd[256];
    int t = threadIdx.x;
    int e = blockIdx.x * 256 + t;
    int b = blockIdx.z;
    const float* p = x + ((size_t)(b * S_LEN + blockIdx.y * 256)) * EMB + e;
    float cs = 0.f;
    double ds = 0.0, dq = 0.0;
#pragma unroll 4
    for (int i = 0; i < 256; i++) {
        float v = p[(size_t)i * EMB];
        cs += v;
        ds += (double)v;
        dq += (double)v * (double)v;
    }
    g_colpart[(b * 8 + blockIdx.y) * EMB + e] = cs;
    sd[t] = ds; __syncthreads();
    for (int o = 128; o > 0; o >>= 1) { if (t < o) sd[t] += sd[t + o]; __syncthreads(); }
    double tot = sd[0]; __syncthreads();
    sd[t] = dq; __syncthreads();
    for (int o = 128; o > 0; o >>= 1) { if (t < o) sd[t] += sd[t + o]; __syncthreads(); }
    if (t == 0) {
        int bi = b * 64 + blockIdx.y * 8 + blockIdx.x;
        g_psum[bi] = tot;
        g_psq[bi]  = sd[0];
    }
}

__global__ void window_kernel(const float* __restrict__ w_c1, const float* __restrict__ w_c2) {
    __shared__ float  xm[2 * EMB];
    __shared__ float  red[512];
    __shared__ double dred[64];
    __shared__ float  varn[2];
    __shared__ float  lgv[2];
    int t = threadIdx.x;

    for (int idx = t; idx < 2 * EMB; idx += 512) {
        int b = idx >> 11, e = idx & 2047;
        float s = 0.f;
#pragma unroll
        for (int c = 0; c < 8; c++) s += g_colpart[(b * 8 + c) * EMB + e];
        xm[idx] = s * (1.0f / (float)S_LEN);
    }

    for (int b = 0; b < 2; b++) {
        __syncthreads();
        if (t < 64) dred[t] = g_psum[b * 64 + t];
        __syncthreads();
        for (int o = 32; o > 0; o >>= 1) { if (t < o) dred[t] += dred[t + o]; __syncthreads(); }
        double sum = dred[0];
        __syncthreads();
        if (t < 64) dred[t] = g_psq[b * 64 + t];
        __syncthreads();
        for (int o = 32; o > 0; o >>= 1) { if (t < o) dred[t] += dred[t + o]; __syncthreads(); }
        if (t == 0) {
            double N = (double)S_LEN * (double)EMB;
            float v = (float)((dred[0] - sum * sum / N) / (N - 1.0));
            varn[b] = 1.0f / (1.0f + expf(-(v * 10.0f - 5.0f)));
        }
    }
    __syncthreads();

    float acc0 = 0.f, acc1 = 0.f;
    const float* wr = w_c1 + (size_t)t * EMB;
    for (int e = 0; e < EMB; e++) {
        float w = wr[e];
        acc0 = fmaf(xm[e], w, acc0);
        acc1 = fmaf(xm[EMB + e], w, acc1);
    }
    float w2 = w_c2[t];
    float h0 = acc0 / (1.0f + expf(-acc0));
    float h1 = acc1 / (1.0f + expf(-acc1));

    red[t] = h0 * w2; __syncthreads();
    for (int o = 256; o > 0; o >>= 1) { if (t < o) red[t] += red[t + o]; __syncthreads(); }
    if (t == 0) lgv[0] = red[0];
    __syncthreads();
    red[t] = h1 * w2; __syncthreads();
    for (int o = 256; o > 0; o >>= 1) { if (t < o) red[t] += red[t + o]; __syncthreads(); }
    if (t == 0) {
        lgv[1] = red[0];
        float l0 = 1.0f / (1.0f + expf(-lgv[0]));
        float l1 = 1.0f / (1.0f + expf(-lgv[1]));
        float wf0 = 64.0f + 0.5f * (varn[0] + l0) * 192.0f;
        float wf1 = 64.0f + 0.5f * (varn[1] + l1) * 192.0f;
        int win = (int)(0.5f * (wf0 + wf1));
        if (win > S_LEN) win = S_LEN;
        if (win < 64) win = 64;
        g_window = win;
    }
}

// C[M,N] = A[M,K] * B[N,K]^T
__global__ __launch_bounds__(256) void sgemm_tn(const float* __restrict__ A,
                                                const float* __restrict__ B,
                                                float* __restrict__ C,
                                                int M, int N, int K)
{
    __shared__ float As[2][16][132];
    __shared__ float Bs[2][16][132];
    const int t  = threadIdx.x;
    const int m0 = blockIdx.y * 128;
    const int n0 = blockIdx.x * 128;
    const int tx = t & 15;
    const int ty = t >> 4;
    const int lr = t >> 2;
    const int lk = (t & 3) * 4;

    const float* Ap = A + (size_t)(m0 + lr) * K + lk;
    const float* Bp = B + (size_t)(n0 + lr) * K + lk;
    const size_t half = (size_t)64 * K;

    float c[8][8];
#pragma unroll
    for (int i = 0; i < 8; i++)
#pragma unroll
        for (int j = 0; j < 8; j++) c[i][j] = 0.f;

    float4 pa0 = *(const float4*)(Ap);
    float4 pa1 = *(const float4*)(Ap + half);
    float4 pb0 = *(const float4*)(Bp);
    float4 pb1 = *(const float4*)(Bp + half);

    int buf = 0;
    As[0][lk+0][lr]    = pa0.x; As[0][lk+1][lr]    = pa0.y; As[0][lk+2][lr]    = pa0.z; As[0][lk+3][lr]    = pa0.w;
    As[0][lk+0][lr+64] = pa1.x; As[0][lk+1][lr+64] = pa1.y; As[0][lk+2][lr+64] = pa1.z; As[0][lk+3][lr+64] = pa1.w;
    Bs[0][lk+0][lr]    = pb0.x; Bs[0][lk+1][lr]    = pb0.y; Bs[0][lk+2][lr]    = pb0.z; Bs[0][lk+3][lr]    = pb0.w;
    Bs[0][lk+0][lr+64] = pb1.x; Bs[0][lk+1][lr+64] = pb1.y; Bs[0][lk+2][lr+64] = pb1.z; Bs[0][lk+3][lr+64] = pb1.w;
    __syncthreads();

    const int nkt = K >> 4;
    for (int kt = 0; kt < nkt; kt++) {
        if (kt + 1 < nkt) {
            const float* a = Ap + (size_t)(kt + 1) * 16;
            const float* b = Bp + (size_t)(kt + 1) * 16;
            pa0 = *(const float4*)(a);
            pa1 = *(const float4*)(a + half);
            pb0 = *(const float4*)(b);
            pb1 = *(const float4*)(b + half);
        }
#pragma unroll
        for (int kk = 0; kk < 16; kk++) {
            float a[8], bb[8];
            *(float4*)&a[0]  = *(const float4*)&As[buf][kk][ty * 8];
            *(float4*)&a[4]  = *(const float4*)&As[buf][kk][ty * 8 + 4];
            *(float4*)&bb[0] = *(const float4*)&Bs[buf][kk][tx * 8];
            *(float4*)&bb[4] = *(const float4*)&Bs[buf][kk][tx * 8 + 4];
#pragma unroll
            for (int i = 0; i < 8; i++)
#pragma unroll
                for (int j = 0; j < 8; j++)
                    c[i][j] = fmaf(a[i], bb[j], c[i][j]);
        }
        if (kt + 1 < nkt) {
            buf ^= 1;
            As[buf][lk+0][lr]    = pa0.x; As[buf][lk+1][lr]    = pa0.y; As[buf][lk+2][lr]    = pa0.z; As[buf][lk+3][lr]    = pa0.w;
            As[buf][lk+0][lr+64] = pa1.x; As[buf][lk+1][lr+64] = pa1.y; As[buf][lk+2][lr+64] = pa1.z; As[buf][lk+3][lr+64] = pa1.w;
            Bs[buf][lk+0][lr]    = pb0.x; Bs[buf][lk+1][lr]    = pb0.y; Bs[buf][lk+2][lr]    = pb0.z; Bs[buf][lk+3][lr]    = pb0.w;
            Bs[buf][lk+0][lr+64] = pb1.x; Bs[buf][lk+1][lr+64] = pb1.y; Bs[buf][lk+2][lr+64] = pb1.z; Bs[buf][lk+3][lr+64] = pb1.w;
            __syncthreads();
        }
    }

#pragma unroll
    for (int i = 0; i < 8; i++) {
        float* cp = C + (size_t)(m0 + ty * 8 + i) * N + n0 + tx * 8;
        *(float4*)cp       = make_float4(c[i][0], c[i][1], c[i][2], c[i][3]);
        *((float4*)cp + 1) = make_float4(c[i][4], c[i][5], c[i][6], c[i][7]);
    }
}

__global__ void rope_apply_kernel() {
    int idx = blockIdx.x * blockDim.x + threadIdx.x;
    if (idx >= MROWS * 2048) return;
    int r    = idx >> 11;
    int pp   = idx & 2047;
    int part = pp >> 10;      // 0=q, 1=k
    int pi   = pp & 1023;
    int h    = pi >> 6;
    int i    = pi & 63;
    int s    = r & (S_LEN - 1);
    int j0   = (2 * i) & 63;
    float c0 = g_cos[s * 64 + j0],     sn0 = g_sin[s * 64 + j0];
    float c1 = g_cos[s * 64 + j0 + 1], sn1 = g_sin[s * 64 + j0 + 1];
    float* p = g_qkv + (size_t)r * QKV_N + part * EMB + h * HDIM + 2 * i;
    float2 v = *(float2*)p;
    float2 o;
    o.x = v.x * c0 - v.y * sn0;
    o.y = v.y * c1 + v.x * sn1;
    *(float2*)p = o;
}

#define TQ 64
#define TK 32

struct AttnSm {
    float qs[HDIM][TQ];
    float ks[HDIM][TK];
    float vs[TK][HDIM];
    float ss[TQ][TK + 1];
    float rowscale[TQ];
    float rowlinv[TQ];
};

__global__ __launch_bounds__(256) void attn_kernel(float* __restrict__ out) {
    extern __shared__ char smraw[];
    AttnSm* sm = (AttnSm*)smraw;
    const int t  = threadIdx.x;
    const int q0 = blockIdx.x * TQ;
    const int h  = blockIdx.y;
    const int b  = blockIdx.z;
    const int w  = g_window;
    const float scale = 0.08838834764831845f;

    const float* qbase = g_qkv + (size_t)b * S_LEN * QKV_N + (size_t)h * HDIM;
    const float* kbase = qbase + EMB;
    const float* vbase = qbase + 2 * EMB;

    {
        int q  = t & 63;
        int dg = t >> 6;
        const float* src = qbase + (size_t)(q0 + q) * QKV_N + dg * 32;
#pragma unroll
        for (int i = 0; i < 8; i++) {
            float4 v = *(const float4*)(src + i * 4);
            int d = dg * 32 + i * 4;
            sm->qs[d+0][q] = v.x; sm->qs[d+1][q] = v.y; sm->qs[d+2][q] = v.z; sm->qs[d+3][q] = v.w;
        }
    }

    float o[4][8];
#pragma unroll
    for (int i = 0; i < 4; i++)
#pragma unroll
        for (int j = 0; j < 8; j++) o[i][j] = 0.f;
    float m = -1e30f, l = 0.f;

    const int qg  = t & 15;
    const int kg  = t >> 4;
    const int dg2 = t >> 4;

    int lo  = q0 - w + 1; if (lo < 0) lo = 0;
    int kc0 = lo & ~(TK - 1);
    int kc1 = q0 + TQ - 1;

    __syncthreads();

    for (int kc = kc0; kc <= kc1; kc += TK) {
        {
            int j  = t & 31;
            int dg = t >> 5;
            const float* src = kbase + (size_t)(kc + j) * QKV_N + dg * 16;
#pragma unroll
            for (int i = 0; i < 4; i++) {
                float4 v = *(const float4*)(src + i * 4);
                int d = dg * 16 + i * 4;
                sm->ks[d+0][j] = v.x; sm->ks[d+1][j] = v.y; sm->ks[d+2][j] = v.z; sm->ks[d+3][j] = v.w;
            }
            int j2 = t >> 3;
            int dv = (t & 7) * 16;
            const float* vsrc = vbase + (size_t)(kc + j2) * QKV_N + dv;
#pragma unroll
            for (int i = 0; i < 4; i++)
                *(float4*)&sm->vs[j2][dv + i * 4] = *(const float4*)(vsrc + i * 4);
        }
        __syncthreads();

        float acc[4][2] = {{0,0},{0,0},{0,0},{0,0}};
#pragma unroll 4
        for (int d = 0; d < HDIM; d++) {
            float4 a = *(const float4*)&sm->qs[d][qg * 4];
            float b0 = sm->ks[d][kg * 2];
            float b1 = sm->ks[d][kg * 2 + 1];
            acc[0][0] = fmaf(a.x, b0, acc[0][0]); acc[0][1] = fmaf(a.x, b1, acc[0][1]);
            acc[1][0] = fmaf(a.y, b0, acc[1][0]); acc[1][1] = fmaf(a.y, b1, acc[1][1]);
            acc[2][0] = fmaf(a.z, b0, acc[2][0]); acc[2][1] = fmaf(a.z, b1, acc[2][1]);
            acc[3][0] = fmaf(a.w, b0, acc[3][0]); acc[3][1] = fmaf(a.w, b1, acc[3][1]);
        }
#pragma unroll
        for (int i = 0; i < 4; i++) {
            sm->ss[qg * 4 + i][kg * 2 + 0] = acc[i][0] * scale;
            sm->ss[qg * 4 + i][kg * 2 + 1] = acc[i][1] * scale;
        }
        __syncthreads();

        if (t < TQ) {
            int gq  = q0 + t;
            int klo = gq - w + 1;
            float mnew = m;
#pragma unroll 8
            for (int j = 0; j < TK; j++) {
                int gk = kc + j;
                if (gk >= klo && gk <= gq) mnew = fmaxf(mnew, sm->ss[t][j]);
            }
            float sc = expf(m - mnew);
            float lsum = 0.f;
#pragma unroll 8
            for (int j = 0; j < TK; j++) {
                int gk = kc + j;
                float p = 0.f;
                if (gk >= klo && gk <= gq) p = expf(sm->ss[t][j] - mnew);
                sm->ss[t][j] = p;
                lsum += p;
            }
            l = l * sc + lsum;
            m = mnew;
            sm->rowscale[t] = sc;
        }
        __syncthreads();

#pragma unroll
        for (int i = 0; i < 4; i++) {
            float sc = sm->rowscale[qg * 4 + i];
#pragma unroll
            for (int j = 0; j < 8; j++) o[i][j] *= sc;
        }
#pragma unroll 4
        for (int j = 0; j < TK; j++) {
            float pv0 = sm->ss[qg * 4 + 0][j];
            float pv1 = sm->ss[qg * 4 + 1][j];
            float pv2 = sm->ss[qg * 4 + 2][j];
            float pv3 = sm->ss[qg * 4 + 3][j];
            float4 v0 = *(const float4*)&sm->vs[j][dg2 * 8];
            float4 v1 = *(const float4*)&sm->vs[j][dg2 * 8 + 4];
            float vv[8] = {v0.x, v0.y, v0.z, v0.w, v1.x, v1.y, v1.z, v1.w};
#pragma unroll
            for (int jj = 0; jj < 8; jj++) {
                o[0][jj] = fmaf(pv0, vv[jj], o[0][jj]);
                o[1][jj] = fmaf(pv1, vv[jj], o[1][jj]);
                o[2][jj] = fmaf(pv2, vv[jj], o[2][jj]);
                o[3][jj] = fmaf(pv3, vv[jj], o[3][jj]);
            }
        }
        __syncthreads();
    }

    if (t < TQ) sm->rowlinv[t] = 1.f / l;
    __syncthreads();

#pragma unroll
    for (int i = 0; i < 4; i++) {
        float li = sm->rowlinv[qg * 4 + i];
        int gq = q0 + qg * 4 + i;
        float* op = out + (size_t)(b * S_LEN + gq) * EMB + h * HDIM + dg2 * 8;
        *(float4*)op       = make_float4(o[i][0] * li, o[i][1] * li, o[i][2] * li, o[i][3] * li);
        *((float4*)op + 1) = make_float4(o[i][4] * li, o[i][5] * li, o[i][6] * li, o[i][7] * li);
    }
}

extern "C" void kernel_launch(void* const* d_in, const int* in_sizes, int n_in,
                              void* d_out, int out_size)
{
    const float* x     = (const float*)d_in[0];
    const float* w_qkv = (const float*)d_in[1];
    const float* w_out = (const float*)d_in[2];
    const float* w_c1  = (const float*)d_in[3];
    const float* w_c2  = (const float*)d_in[4];
    float* out = (float*)d_out;

    static int attr_done = 0;
    if (!attr_done) {
        cudaFuncSetAttribute(attn_kernel, cudaFuncAttributeMaxDynamicSharedMemorySize,
                             (int)sizeof(AttnSm));
        attr_done = 1;
    }

    void* qkvp = 0; cudaGetSymbolAddress(&qkvp, g_qkv);
    void* attp = 0; cudaGetSymbolAddress(&attp, g_attn);

    rope_table_kernel<<<512, 256>>>();
    stats_kernel<<<dim3(8, 8, 2), 256>>>(x);
    window_kernel<<<1, 512>>>(w_c1, w_c2);

    sgemm_tn<<<dim3(QKV_N / 128, MROWS / 128), 256>>>(x, w_qkv, (float*)qkvp,
                                                      MROWS, QKV_N, EMB);
    rope_apply_kernel<<<(MROWS * 2048) / 256, 256>>>();

    attn_kernel<<<dim3(S_LEN / TQ, HEADS, B_SZ), 256, sizeof(AttnSm)>>>((float*)attp);

    sgemm_tn<<<dim3(EMB / 128, MROWS / 128), 256>>>((const float*)attp, w_out, out,
                                                    MROWS, EMB, EMB);
}

// round 9
// speedup vs baseline: 1.7210x; 1.7210x over previous
#include <cuda_runtime.h>
#include <cuda_bf16.h>
#include <math.h>
#include <stdint.h>

#define EMB     2048
#define S_LEN   2048
#define B_SZ    2
#define HEADS   16
#define HDIM    128
#define QKV_N   (3*EMB)
#define MROWS   (B_SZ*S_LEN)

// ---------------- scratch ----------------
__device__ float          g_qkv[25165824];      // 4096 x 6144 fp32
__device__ float          g_attn[8388608];      // 4096 x 2048 fp32
__device__ __nv_bfloat16  g_ah[8388608];        // A hi (x / attn)
__device__ __nv_bfloat16  g_al[8388608];        // A lo
__device__ __nv_bfloat16  g_bh[12582912];       // B hi (w_qkv / w_out)
__device__ __nv_bfloat16  g_bl[12582912];       // B lo
__device__ float  g_cos[S_LEN*64];
__device__ float  g_sin[S_LEN*64];
__device__ float  g_colpart[B_SZ*8*EMB];
__device__ double g_psum[128];
__device__ double g_psq[128];
__device__ int    g_window;

__device__ __forceinline__ uint32_t smem_u32(const void* p) {
    uint32_t a;
    asm("{ .reg .u64 t; cvta.to.shared.u64 t, %1; cvt.u32.u64 %0, t; }" : "=r"(a) : "l"(p));
    return a;
}
__device__ __forceinline__ void lds32(uint32_t& x, uint32_t addr) {
    asm volatile("ld.shared.b32 %0, [%1];" : "=r"(x) : "r"(addr));
}
__device__ __forceinline__ void mma16816(float* c, const uint32_t* a, uint32_t b0, uint32_t b1) {
    asm volatile("mma.sync.aligned.m16n8k16.row.col.f32.bf16.bf16.f32 "
        "{%0,%1,%2,%3}, {%4,%5,%6,%7}, {%8,%9}, {%0,%1,%2,%3};"
        : "+f"(c[0]), "+f"(c[1]), "+f"(c[2]), "+f"(c[3])
        : "r"(a[0]), "r"(a[1]), "r"(a[2]), "r"(a[3]), "r"(b0), "r"(b1));
}

// ---------------- small kernels ----------------
__global__ void rope_table_kernel() {
    int idx = blockIdx.x * blockDim.x + threadIdx.x;
    if (idx >= S_LEN * 64) return;
    int s = idx >> 6, j = idx & 63;
    double inf = exp(-((double)j) * (9.210340371976184 / 64.0));
    double sp, cp;
    sincos((double)s * inf, &sp, &cp);
    g_cos[idx] = (float)cp;
    g_sin[idx] = (float)sp;
}

__global__ void stats_kernel(const float* __restrict__ x) {
    __shared__ double sd[256];
    int t = threadIdx.x;
    int e = blockIdx.x * 256 + t;
    int b = blockIdx.z;
    const float* p = x + ((size_t)(b * S_LEN + blockIdx.y * 256)) * EMB + e;
    float cs = 0.f;
    double ds = 0.0, dq = 0.0;
#pragma unroll 4
    for (int i = 0; i < 256; i++) {
        float v = p[(size_t)i * EMB];
        cs += v;
        ds += (double)v;
        dq += (double)v * (double)v;
    }
    g_colpart[(b * 8 + blockIdx.y) * EMB + e] = cs;
    sd[t] = ds; __syncthreads();
    for (int o = 128; o > 0; o >>= 1) { if (t < o) sd[t] += sd[t + o]; __syncthreads(); }
    double tot = sd[0]; __syncthreads();
    sd[t] = dq; __syncthreads();
    for (int o = 128; o > 0; o >>= 1) { if (t < o) sd[t] += sd[t + o]; __syncthreads(); }
    if (t == 0) {
        int bi = b * 64 + blockIdx.y * 8 + blockIdx.x;
        g_psum[bi] = tot;
        g_psq[bi]  = sd[0];
    }
}

__global__ void window_kernel(const float* __restrict__ w_c1, const float* __restrict__ w_c2) {
    __shared__ float  xm[2 * EMB];
    __shared__ float  red[512];
    __shared__ double dred[64];
    __shared__ float  varn[2];
    __shared__ float  lgv[2];
    int t = threadIdx.x;

    for (int idx = t; idx < 2 * EMB; idx += 512) {
        int b = idx >> 11, e = idx & 2047;
        float s = 0.f;
#pragma unroll
        for (int c = 0; c < 8; c++) s += g_colpart[(b * 8 + c) * EMB + e];
        xm[idx] = s * (1.0f / (float)S_LEN);
    }

    for (int b = 0; b < 2; b++) {
        __syncthreads();
        if (t < 64) dred[t] = g_psum[b * 64 + t];
        __syncthreads();
        for (int o = 32; o > 0; o >>= 1) { if (t < o) dred[t] += dred[t + o]; __syncthreads(); }
        double sum = dred[0];
        __syncthreads();
        if (t < 64) dred[t] = g_psq[b * 64 + t];
        __syncthreads();
        for (int o = 32; o > 0; o >>= 1) { if (t < o) dred[t] += dred[t + o]; __syncthreads(); }
        if (t == 0) {
            double N = (double)S_LEN * (double)EMB;
            float v = (float)((dred[0] - sum * sum / N) / (N - 1.0));
            varn[b] = 1.0f / (1.0f + expf(-(v * 10.0f - 5.0f)));
        }
    }
    __syncthreads();

    float acc0 = 0.f, acc1 = 0.f;
    const float* wr = w_c1 + (size_t)t * EMB;
    for (int e = 0; e < EMB; e++) {
        float w = wr[e];
        acc0 = fmaf(xm[e], w, acc0);
        acc1 = fmaf(xm[EMB + e], w, acc1);
    }
    float w2 = w_c2[t];
    float h0 = acc0 / (1.0f + expf(-acc0));
    float h1 = acc1 / (1.0f + expf(-acc1));

    red[t] = h0 * w2; __syncthreads();
    for (int o = 256; o > 0; o >>= 1) { if (t < o) red[t] += red[t + o]; __syncthreads(); }
    if (t == 0) lgv[0] = red[0];
    __syncthreads();
    red[t] = h1 * w2; __syncthreads();
    for (int o = 256; o > 0; o >>= 1) { if (t < o) red[t] += red[t + o]; __syncthreads(); }
    if (t == 0) {
        lgv[1] = red[0];
        float l0 = 1.0f / (1.0f + expf(-lgv[0]));
        float l1 = 1.0f / (1.0f + expf(-lgv[1]));
        float wf0 = 64.0f + 0.5f * (varn[0] + l0) * 192.0f;
        float wf1 = 64.0f + 0.5f * (varn[1] + l1) * 192.0f;
        int win = (int)(0.5f * (wf0 + wf1));
        if (win > S_LEN) win = S_LEN;
        if (win < 64) win = 64;
        g_window = win;
    }
}

__global__ void split_kernel(const float* __restrict__ src,
                             __nv_bfloat16* __restrict__ hi,
                             __nv_bfloat16* __restrict__ lo, int n4) {
    int i = blockIdx.x * blockDim.x + threadIdx.x;
    if (i >= n4) return;
    float4 v = ((const float4*)src)[i];
    __nv_bfloat16 h0 = __float2bfloat16(v.x);
    __nv_bfloat16 h1 = __float2bfloat16(v.y);
    __nv_bfloat16 h2 = __float2bfloat16(v.z);
    __nv_bfloat16 h3 = __float2bfloat16(v.w);
    __nv_bfloat16 l0 = __float2bfloat16(v.x - __bfloat162float(h0));
    __nv_bfloat16 l1 = __float2bfloat16(v.y - __bfloat162float(h1));
    __nv_bfloat16 l2 = __float2bfloat16(v.z - __bfloat162float(h2));
    __nv_bfloat16 l3 = __float2bfloat16(v.w - __bfloat162float(h3));
    __nv_bfloat162* hp = (__nv_bfloat162*)hi;
    __nv_bfloat162* lp = (__nv_bfloat162*)lo;
    __nv_bfloat162 a; a.x = h0; a.y = h1;
    __nv_bfloat162 b; b.x = h2; b.y = h3;
    hp[2*i] = a; hp[2*i+1] = b;
    a.x = l0; a.y = l1; b.x = l2; b.y = l3;
    lp[2*i] = a; lp[2*i+1] = b;
}

// ---------------- HMMA split-bf16 GEMM: C[M,N] = (Ahi+Alo)(Bhi+Blo)^T ----------------
// 128x128 CTA tile, BK=32, 8 warps (4m x 2n), warp tile 32x64, cp.async double buffer.
#define GBK 32
#define APITCH 80                       // bytes per 32-bf16 row (40 bf16, bank-conflict-free)
#define TILE_B (128*APITCH)             // 10240
#define STAGE_B (4*TILE_B)              // 40960
#define GEMM_SMEM (2*STAGE_B)           // 81920

__global__ __launch_bounds__(256, 2) void gemm_hmma(
    const __nv_bfloat16* __restrict__ Ahi, const __nv_bfloat16* __restrict__ Alo,
    const __nv_bfloat16* __restrict__ Bhi, const __nv_bfloat16* __restrict__ Blo,
    float* __restrict__ C, int N, int K)
{
    extern __shared__ char smem[];
    const uint32_t sb = smem_u32(smem);
    const int t    = threadIdx.x;
    const int m0   = blockIdx.y * 128;
    const int n0   = blockIdx.x * 128;
    const int lane = t & 31;
    const int warp = t >> 5;
    const int wm   = warp & 3;           // 0..3  (m groups of 32)
    const int wn   = warp >> 2;          // 0..1  (n groups of 64)
    const int g    = lane >> 2;          // 0..7
    const int tg   = lane & 3;           // 0..3

    float c[2][8][4];
#pragma unroll
    for (int i = 0; i < 2; i++)
#pragma unroll
        for (int j = 0; j < 8; j++)
#pragma unroll
            for (int q = 0; q < 4; q++) c[i][j][q] = 0.f;

    const int nst = K / GBK;

    // ---- stage issue (cp.async.cg, 16B), 2 chunks per thread per matrix ----
#define ISSUE_STAGE(S, BUF) do { \
        int _k0 = (S) * GBK; \
        uint32_t _dst = sb + (BUF) * STAGE_B; \
        const __nv_bfloat16* _srcs[4] = {Ahi, Alo, Bhi, Blo}; \
        const int _r0[4] = {m0, m0, n0, n0}; \
        _Pragma("unroll") \
        for (int _m = 0; _m < 4; _m++) { \
            _Pragma("unroll") \
            for (int _p = 0; _p < 2; _p++) { \
                int _c = t + _p * 256; \
                int _row = _c >> 2, _j = _c & 3; \
                const void* _gp = _srcs[_m] + (size_t)(_r0[_m] + _row) * K + _k0 + _j * 8; \
                uint32_t _sp = _dst + _m * TILE_B + _row * APITCH + _j * 16; \
                asm volatile("cp.async.cg.shared.global [%0], [%1], 16;" :: "r"(_sp), "l"(_gp)); \
            } \
        } \
        asm volatile("cp.async.commit_group;" ::: "memory"); \
    } while (0)

    ISSUE_STAGE(0, 0);

    for (int s = 0; s < nst; s++) {
        const int buf = s & 1;
        if (s + 1 < nst) {
            ISSUE_STAGE(s + 1, (s + 1) & 1);
            asm volatile("cp.async.wait_group 1;" ::: "memory");
        } else {
            asm volatile("cp.async.wait_group 0;" ::: "memory");
        }
        __syncthreads();

        const uint32_t sAh = sb + buf * STAGE_B;
        const uint32_t sAl = sAh + TILE_B;
        const uint32_t sBh = sAl + TILE_B;
        const uint32_t sBl = sBh + TILE_B;

#pragma unroll
        for (int ks = 0; ks < 2; ks++) {
            const uint32_t kb = ks * 32 + tg * 4;   // byte offset of (k16*16 + tg*2) bf16
            uint32_t ah[2][4], al[2][4];
#pragma unroll
            for (int i = 0; i < 2; i++) {
                uint32_t base = (uint32_t)(wm * 32 + i * 16 + g) * APITCH + kb;
                lds32(ah[i][0], sAh + base);
                lds32(ah[i][1], sAh + base + 8 * APITCH);
                lds32(ah[i][2], sAh + base + 16);
                lds32(ah[i][3], sAh + base + 8 * APITCH + 16);
                lds32(al[i][0], sAl + base);
                lds32(al[i][1], sAl + base + 8 * APITCH);
                lds32(al[i][2], sAl + base + 16);
                lds32(al[i][3], sAl + base + 8 * APITCH + 16);
            }
#pragma unroll
            for (int j = 0; j < 8; j++) {
                uint32_t bb = (uint32_t)(wn * 64 + j * 8 + g) * APITCH + kb;
                uint32_t bh0, bh1, bl0, bl1;
                lds32(bh0, sBh + bb);
                lds32(bh1, sBh + bb + 16);
                lds32(bl0, sBl + bb);
                lds32(bl1, sBl + bb + 16);
#pragma unroll
                for (int i = 0; i < 2; i++) {
                    mma16816(c[i][j], ah[i], bh0, bh1);
                    mma16816(c[i][j], ah[i], bl0, bl1);
                    mma16816(c[i][j], al[i], bh0, bh1);
                }
            }
        }
        __syncthreads();
    }
#undef ISSUE_STAGE

#pragma unroll
    for (int i = 0; i < 2; i++) {
#pragma unroll
        for (int j = 0; j < 8; j++) {
            int row = m0 + wm * 32 + i * 16 + g;
            int col = n0 + wn * 64 + j * 8 + tg * 2;
            float* p = C + (size_t)row * N + col;
            float2 v0; v0.x = c[i][j][0]; v0.y = c[i][j][1];
            float2 v1; v1.x = c[i][j][2]; v1.y = c[i][j][3];
            *(float2*)p = v0;
            *(float2*)(p + (size_t)8 * N) = v1;
        }
    }
}

// ---------------- RoPE apply ----------------
__global__ void rope_apply_kernel() {
    int idx = blockIdx.x * blockDim.x + threadIdx.x;
    if (idx >= MROWS * 2048) return;
    int r    = idx >> 11;
    int pp   = idx & 2047;
    int part = pp >> 10;
    int pi   = pp & 1023;
    int h    = pi >> 6;
    int i    = pi & 63;
    int s    = r & (S_LEN - 1);
    int j0   = (2 * i) & 63;
    float c0 = g_cos[s * 64 + j0],     sn0 = g_sin[s * 64 + j0];
    float c1 = g_cos[s * 64 + j0 + 1], sn1 = g_sin[s * 64 + j0 + 1];
    float* p = g_qkv + (size_t)r * QKV_N + part * EMB + h * HDIM + 2 * i;
    float2 v = *(float2*)p;
    float2 o;
    o.x = v.x * c0 - v.y * sn0;
    o.y = v.y * c1 + v.x * sn1;
    *(float2*)p = o;
}

// ---------------- windowed attention ----------------
#define TQ 64
#define TK 32

struct AttnSm {
    float qs[HDIM][TQ];
    float ks[HDIM][TK];
    float vs[TK][HDIM];
    float ss[TQ][TK + 1];
    float rowscale[TQ];
    float rowlinv[TQ];
};

__global__ __launch_bounds__(256) void attn_kernel(float* __restrict__ out) {
    extern __shared__ char smraw[];
    AttnSm* sm = (AttnSm*)smraw;
    const int t  = threadIdx.x;
    const int q0 = blockIdx.x * TQ;
    const int h  = blockIdx.y;
    const int b  = blockIdx.z;
    const int w  = g_window;
    const float scale = 0.08838834764831845f;

    const float* qbase = g_qkv + (size_t)b * S_LEN * QKV_N + (size_t)h * HDIM;
    const float* kbase = qbase + EMB;
    const float* vbase = qbase + 2 * EMB;

    {
        int q  = t & 63;
        int dg = t >> 6;
        const float* src = qbase + (size_t)(q0 + q) * QKV_N + dg * 32;
#pragma unroll
        for (int i = 0; i < 8; i++) {
            float4 v = *(const float4*)(src + i * 4);
            int d = dg * 32 + i * 4;
            sm->qs[d+0][q] = v.x; sm->qs[d+1][q] = v.y; sm->qs[d+2][q] = v.z; sm->qs[d+3][q] = v.w;
        }
    }

    float o[4][8];
#pragma unroll
    for (int i = 0; i < 4; i++)
#pragma unroll
        for (int j = 0; j < 8; j++) o[i][j] = 0.f;
    float m = -1e30f, l = 0.f;

    const int qg  = t & 15;
    const int kg  = t >> 4;
    const int dg2 = t >> 4;

    int lo  = q0 - w + 1; if (lo < 0) lo = 0;
    int kc0 = lo & ~(TK - 1);
    int kc1 = q0 + TQ - 1;

    __syncthreads();

    for (int kc = kc0; kc <= kc1; kc += TK) {
        {
            int j  = t & 31;
            int dg = t >> 5;
            const float* src = kbase + (size_t)(kc + j) * QKV_N + dg * 16;
#pragma unroll
            for (int i = 0; i < 4; i++) {
                float4 v = *(const float4*)(src + i * 4);
                int d = dg * 16 + i * 4;
                sm->ks[d+0][j] = v.x; sm->ks[d+1][j] = v.y; sm->ks[d+2][j] = v.z; sm->ks[d+3][j] = v.w;
            }
            int j2 = t >> 3;
            int dv = (t & 7) * 16;
            const float* vsrc = vbase + (size_t)(kc + j2) * QKV_N + dv;
#pragma unroll
            for (int i = 0; i < 4; i++)
                *(float4*)&sm->vs[j2][dv + i * 4] = *(const float4*)(vsrc + i * 4);
        }
        __syncthreads();

        float acc[4][2] = {{0,0},{0,0},{0,0},{0,0}};
#pragma unroll 4
        for (int d = 0; d < HDIM; d++) {
            float4 a = *(const float4*)&sm->qs[d][qg * 4];
            float b0 = sm->ks[d][kg * 2];
            float b1 = sm->ks[d][kg * 2 + 1];
            acc[0][0] = fmaf(a.x, b0, acc[0][0]); acc[0][1] = fmaf(a.x, b1, acc[0][1]);
            acc[1][0] = fmaf(a.y, b0, acc[1][0]); acc[1][1] = fmaf(a.y, b1, acc[1][1]);
            acc[2][0] = fmaf(a.z, b0, acc[2][0]); acc[2][1] = fmaf(a.z, b1, acc[2][1]);
            acc[3][0] = fmaf(a.w, b0, acc[3][0]); acc[3][1] = fmaf(a.w, b1, acc[3][1]);
        }
#pragma unroll
        for (int i = 0; i < 4; i++) {
            sm->ss[qg * 4 + i][kg * 2 + 0] = acc[i][0] * scale;
            sm->ss[qg * 4 + i][kg * 2 + 1] = acc[i][1] * scale;
        }
        __syncthreads();

        if (t < TQ) {
            int gq  = q0 + t;
            int klo = gq - w + 1;
            float mnew = m;
#pragma unroll 8
            for (int j = 0; j < TK; j++) {
                int gk = kc + j;
                if (gk >= klo && gk <= gq) mnew = fmaxf(mnew, sm->ss[t][j]);
            }
            float sc = expf(m - mnew);
            float lsum = 0.f;
#pragma unroll 8
            for (int j = 0; j < TK; j++) {
                int gk = kc + j;
                float p = 0.f;
                if (gk >= klo && gk <= gq) p = expf(sm->ss[t][j] - mnew);
                sm->ss[t][j] = p;
                lsum += p;
            }
            l = l * sc + lsum;
            m = mnew;
            sm->rowscale[t] = sc;
        }
        __syncthreads();

#pragma unroll
        for (int i = 0; i < 4; i++) {
            float sc = sm->rowscale[qg * 4 + i];
#pragma unroll
            for (int j = 0; j < 8; j++) o[i][j] *= sc;
        }
#pragma unroll 4
        for (int j = 0; j < TK; j++) {
            float pv0 = sm->ss[qg * 4 + 0][j];
            float pv1 = sm->ss[qg * 4 + 1][j];
            float pv2 = sm->ss[qg * 4 + 2][j];
            float pv3 = sm->ss[qg * 4 + 3][j];
            float4 v0 = *(const float4*)&sm->vs[j][dg2 * 8];
            float4 v1 = *(const float4*)&sm->vs[j][dg2 * 8 + 4];
            float vv[8] = {v0.x, v0.y, v0.z, v0.w, v1.x, v1.y, v1.z, v1.w};
#pragma unroll
            for (int jj = 0; jj < 8; jj++) {
                o[0][jj] = fmaf(pv0, vv[jj], o[0][jj]);
                o[1][jj] = fmaf(pv1, vv[jj], o[1][jj]);
                o[2][jj] = fmaf(pv2, vv[jj], o[2][jj]);
                o[3][jj] = fmaf(pv3, vv[jj], o[3][jj]);
            }
        }
        __syncthreads();
    }

    if (t < TQ) sm->rowlinv[t] = 1.f / l;
    __syncthreads();

#pragma unroll
    for (int i = 0; i < 4; i++) {
        float li = sm->rowlinv[qg * 4 + i];
        int gq = q0 + qg * 4 + i;
        float* op = out + (size_t)(b * S_LEN + gq) * EMB + h * HDIM + dg2 * 8;
        *(float4*)op       = make_float4(o[i][0] * li, o[i][1] * li, o[i][2] * li, o[i][3] * li);
        *((float4*)op + 1) = make_float4(o[i][4] * li, o[i][5] * li, o[i][6] * li, o[i][7] * li);
    }
}

// ---------------- launcher ----------------
extern "C" void kernel_launch(void* const* d_in, const int* in_sizes, int n_in,
                              void* d_out, int out_size)
{
    const float* x     = (const float*)d_in[0];
    const float* w_qkv = (const float*)d_in[1];
    const float* w_out = (const float*)d_in[2];
    const float* w_c1  = (const float*)d_in[3];
    const float* w_c2  = (const float*)d_in[4];
    float* out = (float*)d_out;

    static int attr_done = 0;
    if (!attr_done) {
        cudaFuncSetAttribute(attn_kernel, cudaFuncAttributeMaxDynamicSharedMemorySize,
                             (int)sizeof(AttnSm));
        cudaFuncSetAttribute(gemm_hmma, cudaFuncAttributeMaxDynamicSharedMemorySize,
                             GEMM_SMEM);
        attr_done = 1;
    }

    void* qkvp = 0; cudaGetSymbolAddress(&qkvp, g_qkv);
    void* attp = 0; cudaGetSymbolAddress(&attp, g_attn);
    void* ahp  = 0; cudaGetSymbolAddress(&ahp,  g_ah);
    void* alp  = 0; cudaGetSymbolAddress(&alp,  g_al);
    void* bhp  = 0; cudaGetSymbolAddress(&bhp,  g_bh);
    void* blp  = 0; cudaGetSymbolAddress(&blp,  g_bl);

    __nv_bfloat16* ah = (__nv_bfloat16*)ahp;
    __nv_bfloat16* al = (__nv_bfloat16*)alp;
    __nv_bfloat16* bh = (__nv_bfloat16*)bhp;
    __nv_bfloat16* bl = (__nv_bfloat16*)blp;

    rope_table_kernel<<<512, 256>>>();
    stats_kernel<<<dim3(8, 8, 2), 256>>>(x);
    window_kernel<<<1, 512>>>(w_c1, w_c2);

    // GEMM1: qkv = x @ w_qkv^T   (M=4096, N=6144, K=2048)
    split_kernel<<<(MROWS * EMB / 4 + 255) / 256, 256>>>(x, ah, al, MROWS * EMB / 4);
    split_kernel<<<(QKV_N * EMB / 4 + 255) / 256, 256>>>(w_qkv, bh, bl, QKV_N * EMB / 4);
    gemm_hmma<<<dim3(QKV_N / 128, MROWS / 128), 256, GEMM_SMEM>>>(
        ah, al, bh, bl, (float*)qkvp, QKV_N, EMB);

    rope_apply_kernel<<<(MROWS * 2048) / 256, 256>>>();

    attn_kernel<<<dim3(S_LEN / TQ, HEADS, B_SZ), 256, sizeof(AttnSm)>>>((float*)attp);

    // GEMM2: out = attn @ w_out^T  (M=4096, N=2048, K=2048)
    split_kernel<<<(MROWS * EMB / 4 + 255) / 256, 256>>>((const float*)attp, ah, al, MROWS * EMB / 4);
    split_kernel<<<(EMB * EMB / 4 + 255) / 256, 256>>>(w_out, bh, bl, EMB * EMB / 4);
    gemm_hmma<<<dim3(EMB / 128, MROWS / 128), 256, GEMM_SMEM>>>(
        ah, al, bh, bl, out, EMB, EMB);
}

// round 10
// speedup vs baseline: 1.8279x; 1.0621x over previous
#include <cuda_runtime.h>
#include <cuda_bf16.h>
#include <math.h>
#include <stdint.h>

#define EMB     2048
#define S_LEN   2048
#define B_SZ    2
#define HEADS   16
#define HDIM    128
#define QKV_N   (3*EMB)
#define MROWS   (B_SZ*S_LEN)

// ---------------- scratch ----------------
__device__ float          g_qkv[25165824];      // 4096 x 6144 fp32
__device__ __nv_bfloat16  g_ah[8388608];        // A hi (x / attn-out)
__device__ __nv_bfloat16  g_al[8388608];        // A lo
__device__ __nv_bfloat16  g_bh[12582912];       // B hi (w_qkv / w_out)
__device__ __nv_bfloat16  g_bl[12582912];       // B lo
__device__ float  g_cos[S_LEN*64];
__device__ float  g_sin[S_LEN*64];
__device__ float  g_colpart[B_SZ*8*EMB];
__device__ double g_psum[128];
__device__ double g_psq[128];
__device__ int    g_window;

__device__ __forceinline__ uint32_t smem_u32(const void* p) {
    uint32_t a;
    asm("{ .reg .u64 t; cvta.to.shared.u64 t, %1; cvt.u32.u64 %0, t; }" : "=r"(a) : "l"(p));
    return a;
}
__device__ __forceinline__ void ldsm_x4(uint32_t* r, uint32_t addr) {
    asm volatile("ldmatrix.sync.aligned.m8n8.x4.shared.b16 {%0,%1,%2,%3}, [%4];"
        : "=r"(r[0]), "=r"(r[1]), "=r"(r[2]), "=r"(r[3]) : "r"(addr));
}
__device__ __forceinline__ void mma16816(float* c, const uint32_t* a, uint32_t b0, uint32_t b1) {
    asm volatile("mma.sync.aligned.m16n8k16.row.col.f32.bf16.bf16.f32 "
        "{%0,%1,%2,%3}, {%4,%5,%6,%7}, {%8,%9}, {%0,%1,%2,%3};"
        : "+f"(c[0]), "+f"(c[1]), "+f"(c[2]), "+f"(c[3])
        : "r"(a[0]), "r"(a[1]), "r"(a[2]), "r"(a[3]), "r"(b0), "r"(b1));
}

// ---------------- small kernels ----------------
__global__ void rope_table_kernel() {
    int idx = blockIdx.x * blockDim.x + threadIdx.x;
    if (idx >= S_LEN * 64) return;
    int s = idx >> 6, j = idx & 63;
    double inf = exp(-((double)j) * (9.210340371976184 / 64.0));
    double sp, cp;
    sincos((double)s * inf, &sp, &cp);
    g_cos[idx] = (float)cp;
    g_sin[idx] = (float)sp;
}

__global__ void stats_kernel(const float* __restrict__ x) {
    __shared__ double sd[256];
    int t = threadIdx.x;
    int e = blockIdx.x * 256 + t;
    int b = blockIdx.z;
    const float* p = x + ((size_t)(b * S_LEN + blockIdx.y * 256)) * EMB + e;
    float cs = 0.f;
    double ds = 0.0, dq = 0.0;
#pragma unroll 4
    for (int i = 0; i < 256; i++) {
        float v = p[(size_t)i * EMB];
        cs += v;
        ds += (double)v;
        dq += (double)v * (double)v;
    }
    g_colpart[(b * 8 + blockIdx.y) * EMB + e] = cs;
    sd[t] = ds; __syncthreads();
    for (int o = 128; o > 0; o >>= 1) { if (t < o) sd[t] += sd[t + o]; __syncthreads(); }
    double tot = sd[0]; __syncthreads();
    sd[t] = dq; __syncthreads();
    for (int o = 128; o > 0; o >>= 1) { if (t < o) sd[t] += sd[t + o]; __syncthreads(); }
    if (t == 0) {
        int bi = b * 64 + blockIdx.y * 8 + blockIdx.x;
        g_psum[bi] = tot;
        g_psq[bi]  = sd[0];
    }
}

__global__ void window_kernel(const float* __restrict__ w_c1, const float* __restrict__ w_c2) {
    __shared__ float  xm[2 * EMB];
    __shared__ float  red[512];
    __shared__ double dred[64];
    __shared__ float  varn[2];
    __shared__ float  lgv[2];
    int t = threadIdx.x;

    for (int idx = t; idx < 2 * EMB; idx += 512) {
        int b = idx >> 11, e = idx & 2047;
        float s = 0.f;
#pragma unroll
        for (int c = 0; c < 8; c++) s += g_colpart[(b * 8 + c) * EMB + e];
        xm[idx] = s * (1.0f / (float)S_LEN);
    }

    for (int b = 0; b < 2; b++) {
        __syncthreads();
        if (t < 64) dred[t] = g_psum[b * 64 + t];
        __syncthreads();
        for (int o = 32; o > 0; o >>= 1) { if (t < o) dred[t] += dred[t + o]; __syncthreads(); }
        double sum = dred[0];
        __syncthreads();
        if (t < 64) dred[t] = g_psq[b * 64 + t];
        __syncthreads();
        for (int o = 32; o > 0; o >>= 1) { if (t < o) dred[t] += dred[t + o]; __syncthreads(); }
        if (t == 0) {
            double N = (double)S_LEN * (double)EMB;
            float v = (float)((dred[0] - sum * sum / N) / (N - 1.0));
            varn[b] = 1.0f / (1.0f + expf(-(v * 10.0f - 5.0f)));
        }
    }
    __syncthreads();

    float acc0 = 0.f, acc1 = 0.f;
    const float* wr = w_c1 + (size_t)t * EMB;
    for (int e = 0; e < EMB; e++) {
        float w = wr[e];
        acc0 = fmaf(xm[e], w, acc0);
        acc1 = fmaf(xm[EMB + e], w, acc1);
    }
    float w2 = w_c2[t];
    float h0 = acc0 / (1.0f + expf(-acc0));
    float h1 = acc1 / (1.0f + expf(-acc1));

    red[t] = h0 * w2; __syncthreads();
    for (int o = 256; o > 0; o >>= 1) { if (t < o) red[t] += red[t + o]; __syncthreads(); }
    if (t == 0) lgv[0] = red[0];
    __syncthreads();
    red[t] = h1 * w2; __syncthreads();
    for (int o = 256; o > 0; o >>= 1) { if (t < o) red[t] += red[t + o]; __syncthreads(); }
    if (t == 0) {
        lgv[1] = red[0];
        float l0 = 1.0f / (1.0f + expf(-lgv[0]));
        float l1 = 1.0f / (1.0f + expf(-lgv[1]));
        float wf0 = 64.0f + 0.5f * (varn[0] + l0) * 192.0f;
        float wf1 = 64.0f + 0.5f * (varn[1] + l1) * 192.0f;
        int win = (int)(0.5f * (wf0 + wf1));
        if (win > S_LEN) win = S_LEN;
        if (win < 64) win = 64;
        g_window = win;
    }
}

__global__ void split_kernel(const float* __restrict__ src,
                             __nv_bfloat16* __restrict__ hi,
                             __nv_bfloat16* __restrict__ lo, int n4) {
    int i = blockIdx.x * blockDim.x + threadIdx.x;
    if (i >= n4) return;
    float4 v = ((const float4*)src)[i];
    __nv_bfloat16 h0 = __float2bfloat16(v.x);
    __nv_bfloat16 h1 = __float2bfloat16(v.y);
    __nv_bfloat16 h2 = __float2bfloat16(v.z);
    __nv_bfloat16 h3 = __float2bfloat16(v.w);
    __nv_bfloat16 l0 = __float2bfloat16(v.x - __bfloat162float(h0));
    __nv_bfloat16 l1 = __float2bfloat16(v.y - __bfloat162float(h1));
    __nv_bfloat16 l2 = __float2bfloat16(v.z - __bfloat162float(h2));
    __nv_bfloat16 l3 = __float2bfloat16(v.w - __bfloat162float(h3));
    __nv_bfloat162* hp = (__nv_bfloat162*)hi;
    __nv_bfloat162* lp = (__nv_bfloat162*)lo;
    __nv_bfloat162 a; a.x = h0; a.y = h1;
    __nv_bfloat162 b; b.x = h2; b.y = h3;
    hp[2*i] = a; hp[2*i+1] = b;
    a.x = l0; a.y = l1; b.x = l2; b.y = l3;
    lp[2*i] = a; lp[2*i+1] = b;
}

// ---------------- HMMA split-bf16 GEMM (ldmatrix fragment loads) ----------------
#define GBK 32
#define APITCH 80
#define TILE_B (128*APITCH)
#define STAGE_B (4*TILE_B)
#define GEMM_SMEM (2*STAGE_B)

__global__ __launch_bounds__(256, 2) void gemm_hmma(
    const __nv_bfloat16* __restrict__ Ahi, const __nv_bfloat16* __restrict__ Alo,
    const __nv_bfloat16* __restrict__ Bhi, const __nv_bfloat16* __restrict__ Blo,
    float* __restrict__ C, int N, int K)
{
    extern __shared__ char smem[];
    const uint32_t sb = smem_u32(smem);
    const int t    = threadIdx.x;
    const int m0   = blockIdx.y * 128;
    const int n0   = blockIdx.x * 128;
    const int lane = t & 31;
    const int warp = t >> 5;
    const int wm   = warp & 3;
    const int wn   = warp >> 2;
    const int g    = lane >> 2;
    const int tg   = lane & 3;

    // ldmatrix lane-relative offsets (bytes within a tile)
    uint32_t aoff[2], boff[4];
#pragma unroll
    for (int i = 0; i < 2; i++)
        aoff[i] = (uint32_t)(wm * 32 + i * 16 + (lane & 15)) * APITCH + (lane >> 4) * 16;
#pragma unroll
    for (int jp = 0; jp < 4; jp++)
        boff[jp] = (uint32_t)(wn * 64 + jp * 16 + ((lane >> 4) & 1) * 8 + (lane & 7)) * APITCH
                 + ((lane >> 3) & 1) * 16;

    float c[2][8][4];
#pragma unroll
    for (int i = 0; i < 2; i++)
#pragma unroll
        for (int j = 0; j < 8; j++)
#pragma unroll
            for (int q = 0; q < 4; q++) c[i][j][q] = 0.f;

    const int nst = K / GBK;

#define ISSUE_STAGE(S, BUF) do { \
        int _k0 = (S) * GBK; \
        uint32_t _dst = sb + (BUF) * STAGE_B; \
        const __nv_bfloat16* _srcs[4] = {Ahi, Alo, Bhi, Blo}; \
        const int _r0[4] = {m0, m0, n0, n0}; \
        _Pragma("unroll") \
        for (int _m = 0; _m < 4; _m++) { \
            _Pragma("unroll") \
            for (int _p = 0; _p < 2; _p++) { \
                int _c = t + _p * 256; \
                int _row = _c >> 2, _j = _c & 3; \
                const void* _gp = _srcs[_m] + (size_t)(_r0[_m] + _row) * K + _k0 + _j * 8; \
                uint32_t _sp = _dst + _m * TILE_B + _row * APITCH + _j * 16; \
                asm volatile("cp.async.cg.shared.global [%0], [%1], 16;" :: "r"(_sp), "l"(_gp)); \
            } \
        } \
        asm volatile("cp.async.commit_group;" ::: "memory"); \
    } while (0)

    ISSUE_STAGE(0, 0);

    for (int s = 0; s < nst; s++) {
        const int buf = s & 1;
        if (s + 1 < nst) {
            ISSUE_STAGE(s + 1, (s + 1) & 1);
            asm volatile("cp.async.wait_group 1;" ::: "memory");
        } else {
            asm volatile("cp.async.wait_group 0;" ::: "memory");
        }
        __syncthreads();

        const uint32_t sAh = sb + buf * STAGE_B;
        const uint32_t sAl = sAh + TILE_B;
        const uint32_t sBh = sAl + TILE_B;
        const uint32_t sBl = sBh + TILE_B;

#pragma unroll
        for (int ks = 0; ks < 2; ks++) {
            const uint32_t ko = ks * 32;
            uint32_t ah[2][4], al[2][4];
            ldsm_x4(ah[0], sAh + aoff[0] + ko);
            ldsm_x4(ah[1], sAh + aoff[1] + ko);
            ldsm_x4(al[0], sAl + aoff[0] + ko);
            ldsm_x4(al[1], sAl + aoff[1] + ko);
#pragma unroll
            for (int jp = 0; jp < 4; jp++) {
                uint32_t bh[4], bl[4];
                ldsm_x4(bh, sBh + boff[jp] + ko);
                ldsm_x4(bl, sBl + boff[jp] + ko);
#pragma unroll
                for (int jj = 0; jj < 2; jj++) {
                    int j = jp * 2 + jj;
#pragma unroll
                    for (int i = 0; i < 2; i++) {
                        mma16816(c[i][j], ah[i], bh[2*jj], bh[2*jj+1]);
                        mma16816(c[i][j], ah[i], bl[2*jj], bl[2*jj+1]);
                        mma16816(c[i][j], al[i], bh[2*jj], bh[2*jj+1]);
                    }
                }
            }
        }
        __syncthreads();
    }
#undef ISSUE_STAGE

#pragma unroll
    for (int i = 0; i < 2; i++) {
#pragma unroll
        for (int j = 0; j < 8; j++) {
            int row = m0 + wm * 32 + i * 16 + g;
            int col = n0 + wn * 64 + j * 8 + tg * 2;
            float* p = C + (size_t)row * N + col;
            float2 v0; v0.x = c[i][j][0]; v0.y = c[i][j][1];
            float2 v1; v1.x = c[i][j][2]; v1.y = c[i][j][3];
            *(float2*)p = v0;
            *(float2*)(p + (size_t)8 * N) = v1;
        }
    }
}

// ---------------- RoPE apply ----------------
__global__ void rope_apply_kernel() {
    int idx = blockIdx.x * blockDim.x + threadIdx.x;
    if (idx >= MROWS * 2048) return;
    int r    = idx >> 11;
    int pp   = idx & 2047;
    int part = pp >> 10;
    int pi   = pp & 1023;
    int h    = pi >> 6;
    int i    = pi & 63;
    int s    = r & (S_LEN - 1);
    int j0   = (2 * i) & 63;
    float c0 = g_cos[s * 64 + j0],     sn0 = g_sin[s * 64 + j0];
    float c1 = g_cos[s * 64 + j0 + 1], sn1 = g_sin[s * 64 + j0 + 1];
    float* p = g_qkv + (size_t)r * QKV_N + part * EMB + h * HDIM + 2 * i;
    float2 v = *(float2*)p;
    float2 o;
    o.x = v.x * c0 - v.y * sn0;
    o.y = v.y * c1 + v.x * sn1;
    *(float2*)p = o;
}

// ---------------- windowed attention (parallel softmax, bf16-split epilogue) ----------------
#define TQ 64
#define TK 32

struct AttnSm {
    float qs[HDIM][TQ];
    float ks[HDIM][TK];
    float vs[TK][HDIM];
    float ss[TQ][TK + 1];
    float rowscale[TQ];
    float rowlinv[TQ];
};

__global__ __launch_bounds__(256, 3) void attn_kernel(__nv_bfloat16* __restrict__ oh,
                                                      __nv_bfloat16* __restrict__ ol) {
    extern __shared__ char smraw[];
    AttnSm* sm = (AttnSm*)smraw;
    const int t  = threadIdx.x;
    const int q0 = blockIdx.x * TQ;
    const int h  = blockIdx.y;
    const int b  = blockIdx.z;
    const int w  = g_window;
    const float scale = 0.08838834764831845f;

    const float* qbase = g_qkv + (size_t)b * S_LEN * QKV_N + (size_t)h * HDIM;
    const float* kbase = qbase + EMB;
    const float* vbase = qbase + 2 * EMB;

    {
        int q  = t & 63;
        int dg = t >> 6;
        const float* src = qbase + (size_t)(q0 + q) * QKV_N + dg * 32;
#pragma unroll
        for (int i = 0; i < 8; i++) {
            float4 v = *(const float4*)(src + i * 4);
            int d = dg * 32 + i * 4;
            sm->qs[d+0][q] = v.x; sm->qs[d+1][q] = v.y; sm->qs[d+2][q] = v.z; sm->qs[d+3][q] = v.w;
        }
    }

    float o[4][8];
#pragma unroll
    for (int i = 0; i < 4; i++)
#pragma unroll
        for (int j = 0; j < 8; j++) o[i][j] = 0.f;
    float m = -1e30f, l = 0.f;        // per-row state, replicated over 4 threads/row

    const int qg  = t & 15;
    const int kg  = t >> 4;
    const int dg2 = t >> 4;
    const int srow = t >> 2;          // softmax row (0..63)
    const int ssub = t & 3;           // 4 threads per row

    int lo  = q0 - w + 1; if (lo < 0) lo = 0;
    int kc0 = lo & ~(TK - 1);
    int kc1 = q0 + TQ - 1;

    __syncthreads();

    for (int kc = kc0; kc <= kc1; kc += TK) {
        {
            int j  = t & 31;
            int dg = t >> 5;
            const float* src = kbase + (size_t)(kc + j) * QKV_N + dg * 16;
#pragma unroll
            for (int i = 0; i < 4; i++) {
                float4 v = *(const float4*)(src + i * 4);
                int d = dg * 16 + i * 4;
                sm->ks[d+0][j] = v.x; sm->ks[d+1][j] = v.y; sm->ks[d+2][j] = v.z; sm->ks[d+3][j] = v.w;
            }
            int j2 = t >> 3;
            int dv = (t & 7) * 16;
            const float* vsrc = vbase + (size_t)(kc + j2) * QKV_N + dv;
#pragma unroll
            for (int i = 0; i < 4; i++)
                *(float4*)&sm->vs[j2][dv + i * 4] = *(const float4*)(vsrc + i * 4);
        }
        __syncthreads();

        float acc[4][2] = {{0,0},{0,0},{0,0},{0,0}};
#pragma unroll 4
        for (int d = 0; d < HDIM; d++) {
            float4 a = *(const float4*)&sm->qs[d][qg * 4];
            float b0 = sm->ks[d][kg * 2];
            float b1 = sm->ks[d][kg * 2 + 1];
            acc[0][0] = fmaf(a.x, b0, acc[0][0]); acc[0][1] = fmaf(a.x, b1, acc[0][1]);
            acc[1][0] = fmaf(a.y, b0, acc[1][0]); acc[1][1] = fmaf(a.y, b1, acc[1][1]);
            acc[2][0] = fmaf(a.z, b0, acc[2][0]); acc[2][1] = fmaf(a.z, b1, acc[2][1]);
            acc[3][0] = fmaf(a.w, b0, acc[3][0]); acc[3][1] = fmaf(a.w, b1, acc[3][1]);
        }
#pragma unroll
        for (int i = 0; i < 4; i++) {
            sm->ss[qg * 4 + i][kg * 2 + 0] = acc[i][0] * scale;
            sm->ss[qg * 4 + i][kg * 2 + 1] = acc[i][1] * scale;
        }
        __syncthreads();

        // parallel online softmax: 4 threads per row, 8 keys each
        {
            int gq  = q0 + srow;
            int klo = gq - w + 1;
            float sv[8];
            float mloc = m;
#pragma unroll
            for (int jj = 0; jj < 8; jj++) {
                int j  = ssub * 8 + jj;
                int gk = kc + j;
                bool keep = (gk >= klo) && (gk <= gq);
                sv[jj] = keep ? sm->ss[srow][j] : -1e30f;
                mloc = fmaxf(mloc, sv[jj]);
            }
            mloc = fmaxf(mloc, __shfl_xor_sync(0xFFFFFFFFu, mloc, 1));
            mloc = fmaxf(mloc, __shfl_xor_sync(0xFFFFFFFFu, mloc, 2));
            float sc = __expf(m - mloc);
            float ls = 0.f;
#pragma unroll
            for (int jj = 0; jj < 8; jj++) {
                int j = ssub * 8 + jj;
                float p = (sv[jj] > -1e29f) ? __expf(sv[jj] - mloc) : 0.f;
                sm->ss[srow][j] = p;
                ls += p;
            }
            ls += __shfl_xor_sync(0xFFFFFFFFu, ls, 1);
            ls += __shfl_xor_sync(0xFFFFFFFFu, ls, 2);
            l = l * sc + ls;
            m = mloc;
            if (ssub == 0) sm->rowscale[srow] = sc;
        }
        __syncthreads();

#pragma unroll
        for (int i = 0; i < 4; i++) {
            float sc = sm->rowscale[qg * 4 + i];
#pragma unroll
            for (int j = 0; j < 8; j++) o[i][j] *= sc;
        }
#pragma unroll 4
        for (int j = 0; j < TK; j++) {
            float pv0 = sm->ss[qg * 4 + 0][j];
            float pv1 = sm->ss[qg * 4 + 1][j];
            float pv2 = sm->ss[qg * 4 + 2][j];
            float pv3 = sm->ss[qg * 4 + 3][j];
            float4 v0 = *(const float4*)&sm->vs[j][dg2 * 8];
            float4 v1 = *(const float4*)&sm->vs[j][dg2 * 8 + 4];
            float vv[8] = {v0.x, v0.y, v0.z, v0.w, v1.x, v1.y, v1.z, v1.w};
#pragma unroll
            for (int jj = 0; jj < 8; jj++) {
                o[0][jj] = fmaf(pv0, vv[jj], o[0][jj]);
                o[1][jj] = fmaf(pv1, vv[jj], o[1][jj]);
                o[2][jj] = fmaf(pv2, vv[jj], o[2][jj]);
                o[3][jj] = fmaf(pv3, vv[jj], o[3][jj]);
            }
        }
        __syncthreads();
    }

    if (ssub == 0) sm->rowlinv[srow] = 1.f / l;
    __syncthreads();

    // epilogue: normalize + bf16 hi/lo split, store directly for GEMM2
#pragma unroll
    for (int i = 0; i < 4; i++) {
        float li = sm->rowlinv[qg * 4 + i];
        int gq = q0 + qg * 4 + i;
        size_t off = (size_t)(b * S_LEN + gq) * EMB + h * HDIM + dg2 * 8;
        union { uint4 u; __nv_bfloat162 h2[4]; } uh, ul;
#pragma unroll
        for (int p = 0; p < 4; p++) {
            float v0 = o[i][2*p]   * li;
            float v1 = o[i][2*p+1] * li;
            __nv_bfloat16 b0 = __float2bfloat16(v0);
            __nv_bfloat16 b1 = __float2bfloat16(v1);
            uh.h2[p] = __halves2bfloat162(b0, b1);
            ul.h2[p] = __halves2bfloat162(
                __float2bfloat16(v0 - __bfloat162float(b0)),
                __float2bfloat16(v1 - __bfloat162float(b1)));
        }
        *(uint4*)(oh + off) = uh.u;
        *(uint4*)(ol + off) = ul.u;
    }
}

// ---------------- launcher ----------------
extern "C" void kernel_launch(void* const* d_in, const int* in_sizes, int n_in,
                              void* d_out, int out_size)
{
    const float* x     = (const float*)d_in[0];
    const float* w_qkv = (const float*)d_in[1];
    const float* w_out = (const float*)d_in[2];
    const float* w_c1  = (const float*)d_in[3];
    const float* w_c2  = (const float*)d_in[4];
    float* out = (float*)d_out;

    static int attr_done = 0;
    if (!attr_done) {
        cudaFuncSetAttribute(attn_kernel, cudaFuncAttributeMaxDynamicSharedMemorySize,
                             (int)sizeof(AttnSm));
        cudaFuncSetAttribute(gemm_hmma, cudaFuncAttributeMaxDynamicSharedMemorySize,
                             GEMM_SMEM);
        attr_done = 1;
    }

    void* qkvp = 0; cudaGetSymbolAddress(&qkvp, g_qkv);
    void* ahp  = 0; cudaGetSymbolAddress(&ahp,  g_ah);
    void* alp  = 0; cudaGetSymbolAddress(&alp,  g_al);
    void* bhp  = 0; cudaGetSymbolAddress(&bhp,  g_bh);
    void* blp  = 0; cudaGetSymbolAddress(&blp,  g_bl);

    __nv_bfloat16* ah = (__nv_bfloat16*)ahp;
    __nv_bfloat16* al = (__nv_bfloat16*)alp;
    __nv_bfloat16* bh = (__nv_bfloat16*)bhp;
    __nv_bfloat16* bl = (__nv_bfloat16*)blp;

    rope_table_kernel<<<512, 256>>>();
    stats_kernel<<<dim3(8, 8, 2), 256>>>(x);
    window_kernel<<<1, 512>>>(w_c1, w_c2);

    // GEMM1: qkv = x @ w_qkv^T
    split_kernel<<<(MROWS * EMB / 4 + 255) / 256, 256>>>(x, ah, al, MROWS * EMB / 4);
    split_kernel<<<(QKV_N * EMB / 4 + 255) / 256, 256>>>(w_qkv, bh, bl, QKV_N * EMB / 4);
    gemm_hmma<<<dim3(QKV_N / 128, MROWS / 128), 256, GEMM_SMEM>>>(
        ah, al, bh, bl, (float*)qkvp, QKV_N, EMB);

    rope_apply_kernel<<<(MROWS * 2048) / 256, 256>>>();

    // attention writes bf16 split of its output directly into ah/al
    attn_kernel<<<dim3(S_LEN / TQ, HEADS, B_SZ), 256, sizeof(AttnSm)>>>(ah, al);

    // GEMM2: out = attn @ w_out^T
    split_kernel<<<(EMB * EMB / 4 + 255) / 256, 256>>>(w_out, bh, bl, EMB * EMB / 4);
    gemm_hmma<<<dim3(EMB / 128, MROWS / 128), 256, GEMM_SMEM>>>(
        ah, al, bh, bl, out, EMB, EMB);
}

// round 11
// speedup vs baseline: 2.0220x; 1.1062x over previous
#include <cuda_runtime.h>
#include <cuda_bf16.h>
#include <math.h>
#include <stdint.h>

#define EMB     2048
#define S_LEN   2048
#define B_SZ    2
#define HEADS   16
#define HDIM    128
#define QKV_N   (3*EMB)
#define MROWS   (B_SZ*S_LEN)

// ---------------- scratch ----------------
__device__ float          g_qkv[25165824];      // 4096 x 6144 fp32
__device__ __nv_bfloat16  g_ah[8388608];        // A hi (x / attn-out)
__device__ __nv_bfloat16  g_al[8388608];        // A lo
__device__ __nv_bfloat16  g_bh[12582912];       // B hi (w_qkv / w_out)
__device__ __nv_bfloat16  g_bl[12582912];       // B lo
__device__ float  g_cos[S_LEN*64];
__device__ float  g_sin[S_LEN*64];
__device__ float  g_colpart[B_SZ*8*EMB];
__device__ double g_psum[128];
__device__ double g_psq[128];
__device__ int    g_window;

__device__ __forceinline__ uint32_t smem_u32(const void* p) {
    uint32_t a;
    asm("{ .reg .u64 t; cvta.to.shared.u64 t, %1; cvt.u32.u64 %0, t; }" : "=r"(a) : "l"(p));
    return a;
}
__device__ __forceinline__ void ldsm_x4(uint32_t* r, uint32_t addr) {
    asm volatile("ldmatrix.sync.aligned.m8n8.x4.shared.b16 {%0,%1,%2,%3}, [%4];"
        : "=r"(r[0]), "=r"(r[1]), "=r"(r[2]), "=r"(r[3]) : "r"(addr));
}
__device__ __forceinline__ void ldsm_x4_t(uint32_t* r, uint32_t addr) {
    asm volatile("ldmatrix.sync.aligned.m8n8.x4.trans.shared.b16 {%0,%1,%2,%3}, [%4];"
        : "=r"(r[0]), "=r"(r[1]), "=r"(r[2]), "=r"(r[3]) : "r"(addr));
}
__device__ __forceinline__ void mma16816(float* c, const uint32_t* a, uint32_t b0, uint32_t b1) {
    asm volatile("mma.sync.aligned.m16n8k16.row.col.f32.bf16.bf16.f32 "
        "{%0,%1,%2,%3}, {%4,%5,%6,%7}, {%8,%9}, {%0,%1,%2,%3};"
        : "+f"(c[0]), "+f"(c[1]), "+f"(c[2]), "+f"(c[3])
        : "r"(a[0]), "r"(a[1]), "r"(a[2]), "r"(a[3]), "r"(b0), "r"(b1));
}
__device__ __forceinline__ uint32_t pack_bf16(float x, float y) {
    __nv_bfloat162 h = __halves2bfloat162(__float2bfloat16(x), __float2bfloat16(y));
    return *(uint32_t*)&h;
}
__device__ __forceinline__ void split2(float x, float y, uint32_t& hi, uint32_t& lo) {
    __nv_bfloat16 hx = __float2bfloat16(x);
    __nv_bfloat16 hy = __float2bfloat16(y);
    __nv_bfloat162 h2 = __halves2bfloat162(hx, hy);
    __nv_bfloat162 l2 = __halves2bfloat162(
        __float2bfloat16(x - __bfloat162float(hx)),
        __float2bfloat16(y - __bfloat162float(hy)));
    hi = *(uint32_t*)&h2;
    lo = *(uint32_t*)&l2;
}

// ---------------- small kernels ----------------
__global__ void rope_table_kernel() {
    int idx = blockIdx.x * blockDim.x + threadIdx.x;
    if (idx >= S_LEN * 64) return;
    int s = idx >> 6, j = idx & 63;
    double inf = exp(-((double)j) * (9.210340371976184 / 64.0));
    double sp, cp;
    sincos((double)s * inf, &sp, &cp);
    g_cos[idx] = (float)cp;
    g_sin[idx] = (float)sp;
}

__global__ void stats_kernel(const float* __restrict__ x) {
    __shared__ double sd[256];
    int t = threadIdx.x;
    int e = blockIdx.x * 256 + t;
    int b = blockIdx.z;
    const float* p = x + ((size_t)(b * S_LEN + blockIdx.y * 256)) * EMB + e;
    float cs = 0.f;
    double ds = 0.0, dq = 0.0;
#pragma unroll 4
    for (int i = 0; i < 256; i++) {
        float v = p[(size_t)i * EMB];
        cs += v;
        ds += (double)v;
        dq += (double)v * (double)v;
    }
    g_colpart[(b * 8 + blockIdx.y) * EMB + e] = cs;
    sd[t] = ds; __syncthreads();
    for (int o = 128; o > 0; o >>= 1) { if (t < o) sd[t] += sd[t + o]; __syncthreads(); }
    double tot = sd[0]; __syncthreads();
    sd[t] = dq; __syncthreads();
    for (int o = 128; o > 0; o >>= 1) { if (t < o) sd[t] += sd[t + o]; __syncthreads(); }
    if (t == 0) {
        int bi = b * 64 + blockIdx.y * 8 + blockIdx.x;
        g_psum[bi] = tot;
        g_psq[bi]  = sd[0];
    }
}

__global__ void window_kernel(const float* __restrict__ w_c1, const float* __restrict__ w_c2) {
    __shared__ float  xm[2 * EMB];
    __shared__ float  red[512];
    __shared__ double dred[64];
    __shared__ float  varn[2];
    __shared__ float  lgv[2];
    int t = threadIdx.x;

    for (int idx = t; idx < 2 * EMB; idx += 512) {
        int b = idx >> 11, e = idx & 2047;
        float s = 0.f;
#pragma unroll
        for (int c = 0; c < 8; c++) s += g_colpart[(b * 8 + c) * EMB + e];
        xm[idx] = s * (1.0f / (float)S_LEN);
    }

    for (int b = 0; b < 2; b++) {
        __syncthreads();
        if (t < 64) dred[t] = g_psum[b * 64 + t];
        __syncthreads();
        for (int o = 32; o > 0; o >>= 1) { if (t < o) dred[t] += dred[t + o]; __syncthreads(); }
        double sum = dred[0];
        __syncthreads();
        if (t < 64) dred[t] = g_psq[b * 64 + t];
        __syncthreads();
        for (int o = 32; o > 0; o >>= 1) { if (t < o) dred[t] += dred[t + o]; __syncthreads(); }
        if (t == 0) {
            double N = (double)S_LEN * (double)EMB;
            float v = (float)((dred[0] - sum * sum / N) / (N - 1.0));
            varn[b] = 1.0f / (1.0f + expf(-(v * 10.0f - 5.0f)));
        }
    }
    __syncthreads();

    float acc0 = 0.f, acc1 = 0.f;
    const float* wr = w_c1 + (size_t)t * EMB;
    for (int e = 0; e < EMB; e++) {
        float w = wr[e];
        acc0 = fmaf(xm[e], w, acc0);
        acc1 = fmaf(xm[EMB + e], w, acc1);
    }
    float w2 = w_c2[t];
    float h0 = acc0 / (1.0f + expf(-acc0));
    float h1 = acc1 / (1.0f + expf(-acc1));

    red[t] = h0 * w2; __syncthreads();
    for (int o = 256; o > 0; o >>= 1) { if (t < o) red[t] += red[t + o]; __syncthreads(); }
    if (t == 0) lgv[0] = red[0];
    __syncthreads();
    red[t] = h1 * w2; __syncthreads();
    for (int o = 256; o > 0; o >>= 1) { if (t < o) red[t] += red[t + o]; __syncthreads(); }
    if (t == 0) {
        lgv[1] = red[0];
        float l0 = 1.0f / (1.0f + expf(-lgv[0]));
        float l1 = 1.0f / (1.0f + expf(-lgv[1]));
        float wf0 = 64.0f + 0.5f * (varn[0] + l0) * 192.0f;
        float wf1 = 64.0f + 0.5f * (varn[1] + l1) * 192.0f;
        int win = (int)(0.5f * (wf0 + wf1));
        if (win > S_LEN) win = S_LEN;
        if (win < 64) win = 64;
        g_window = win;
    }
}

__global__ void split_kernel(const float* __restrict__ src,
                             __nv_bfloat16* __restrict__ hi,
                             __nv_bfloat16* __restrict__ lo, int n4) {
    int i = blockIdx.x * blockDim.x + threadIdx.x;
    if (i >= n4) return;
    float4 v = ((const float4*)src)[i];
    uint32_t h0, l0, h1, l1;
    split2(v.x, v.y, h0, l0);
    split2(v.z, v.w, h1, l1);
    uint2* hp = (uint2*)hi;
    uint2* lp = (uint2*)lo;
    uint2 a; a.x = h0; a.y = h1; hp[i] = a;
    a.x = l0; a.y = l1; lp[i] = a;
}

// ---------------- HMMA split-bf16 GEMM (unchanged from R10) ----------------
#define GBK 32
#define APITCH 80
#define TILE_B (128*APITCH)
#define STAGE_B (4*TILE_B)
#define GEMM_SMEM (2*STAGE_B)

__global__ __launch_bounds__(256, 2) void gemm_hmma(
    const __nv_bfloat16* __restrict__ Ahi, const __nv_bfloat16* __restrict__ Alo,
    const __nv_bfloat16* __restrict__ Bhi, const __nv_bfloat16* __restrict__ Blo,
    float* __restrict__ C, int N, int K)
{
    extern __shared__ char smem[];
    const uint32_t sb = smem_u32(smem);
    const int t    = threadIdx.x;
    const int m0   = blockIdx.y * 128;
    const int n0   = blockIdx.x * 128;
    const int lane = t & 31;
    const int warp = t >> 5;
    const int wm   = warp & 3;
    const int wn   = warp >> 2;
    const int g    = lane >> 2;
    const int tg   = lane & 3;

    uint32_t aoff[2], boff[4];
#pragma unroll
    for (int i = 0; i < 2; i++)
        aoff[i] = (uint32_t)(wm * 32 + i * 16 + (lane & 15)) * APITCH + (lane >> 4) * 16;
#pragma unroll
    for (int jp = 0; jp < 4; jp++)
        boff[jp] = (uint32_t)(wn * 64 + jp * 16 + ((lane >> 4) & 1) * 8 + (lane & 7)) * APITCH
                 + ((lane >> 3) & 1) * 16;

    float c[2][8][4];
#pragma unroll
    for (int i = 0; i < 2; i++)
#pragma unroll
        for (int j = 0; j < 8; j++)
#pragma unroll
            for (int q = 0; q < 4; q++) c[i][j][q] = 0.f;

    const int nst = K / GBK;

#define ISSUE_STAGE(S, BUF) do { \
        int _k0 = (S) * GBK; \
        uint32_t _dst = sb + (BUF) * STAGE_B; \
        const __nv_bfloat16* _srcs[4] = {Ahi, Alo, Bhi, Blo}; \
        const int _r0[4] = {m0, m0, n0, n0}; \
        _Pragma("unroll") \
        for (int _m = 0; _m < 4; _m++) { \
            _Pragma("unroll") \
            for (int _p = 0; _p < 2; _p++) { \
                int _c = t + _p * 256; \
                int _row = _c >> 2, _j = _c & 3; \
                const void* _gp = _srcs[_m] + (size_t)(_r0[_m] + _row) * K + _k0 + _j * 8; \
                uint32_t _sp = _dst + _m * TILE_B + _row * APITCH + _j * 16; \
                asm volatile("cp.async.cg.shared.global [%0], [%1], 16;" :: "r"(_sp), "l"(_gp)); \
            } \
        } \
        asm volatile("cp.async.commit_group;" ::: "memory"); \
    } while (0)

    ISSUE_STAGE(0, 0);

    for (int s = 0; s < nst; s++) {
        const int buf = s & 1;
        if (s + 1 < nst) {
            ISSUE_STAGE(s + 1, (s + 1) & 1);
            asm volatile("cp.async.wait_group 1;" ::: "memory");
        } else {
            asm volatile("cp.async.wait_group 0;" ::: "memory");
        }
        __syncthreads();

        const uint32_t sAh = sb + buf * STAGE_B;
        const uint32_t sAl = sAh + TILE_B;
        const uint32_t sBh = sAl + TILE_B;
        const uint32_t sBl = sBh + TILE_B;

#pragma unroll
        for (int ks = 0; ks < 2; ks++) {
            const uint32_t ko = ks * 32;
            uint32_t ah[2][4], al[2][4];
            ldsm_x4(ah[0], sAh + aoff[0] + ko);
            ldsm_x4(ah[1], sAh + aoff[1] + ko);
            ldsm_x4(al[0], sAl + aoff[0] + ko);
            ldsm_x4(al[1], sAl + aoff[1] + ko);
#pragma unroll
            for (int jp = 0; jp < 4; jp++) {
                uint32_t bh[4], bl[4];
                ldsm_x4(bh, sBh + boff[jp] + ko);
                ldsm_x4(bl, sBl + boff[jp] + ko);
#pragma unroll
                for (int jj = 0; jj < 2; jj++) {
                    int j = jp * 2 + jj;
#pragma unroll
                    for (int i = 0; i < 2; i++) {
                        mma16816(c[i][j], ah[i], bh[2*jj], bh[2*jj+1]);
                        mma16816(c[i][j], ah[i], bl[2*jj], bl[2*jj+1]);
                        mma16816(c[i][j], al[i], bh[2*jj], bh[2*jj+1]);
                    }
                }
            }
        }
        __syncthreads();
    }
#undef ISSUE_STAGE

#pragma unroll
    for (int i = 0; i < 2; i++) {
#pragma unroll
        for (int j = 0; j < 8; j++) {
            int row = m0 + wm * 32 + i * 16 + g;
            int col = n0 + wn * 64 + j * 8 + tg * 2;
            float* p = C + (size_t)row * N + col;
            float2 v0; v0.x = c[i][j][0]; v0.y = c[i][j][1];
            float2 v1; v1.x = c[i][j][2]; v1.y = c[i][j][3];
            *(float2*)p = v0;
            *(float2*)(p + (size_t)8 * N) = v1;
        }
    }
}

// ---------------- HMMA windowed flash attention ----------------
// TQ=128 per CTA, 8 warps x 16 rows; TK=64 chunks; split-bf16 QK and PV.
#define AQP 272         // smem pitch bytes for 128 bf16 + pad

struct AttnSm2 {
    char qh[128 * AQP];
    char ql[128 * AQP];
    char kh[64 * AQP];
    char kl[64 * AQP];
    char vh[64 * AQP];
    char vl[64 * AQP];
};

__global__ __launch_bounds__(256) void attn_mma_kernel(__nv_bfloat16* __restrict__ oh,
                                                       __nv_bfloat16* __restrict__ ol) {
    extern __shared__ char smraw[];
    AttnSm2* sm = (AttnSm2*)smraw;
    const int t    = threadIdx.x;
    const int lane = t & 31;
    const int warp = t >> 5;
    const int q0   = blockIdx.x * 128;
    const int h    = blockIdx.y;
    const int b    = blockIdx.z;
    const int w    = g_window;
    const float scale = 0.08838834764831845f;

    const float* rowbase = g_qkv + (size_t)(b * S_LEN) * QKV_N;

    // ---- stage Q: rope + scale + hi/lo split ----
#pragma unroll
    for (int p = 0; p < 8; p++) {
        int seg = t + p * 256;             // 2048 segs: 128 rows x 16
        int r = seg >> 4, dseg = seg & 15;
        int s_pos = q0 + r;
        const float* src = rowbase + (size_t)s_pos * QKV_N + h * HDIM + dseg * 8;
        float4 v0 = *(const float4*)src;
        float4 v1 = *(const float4*)(src + 4);
        float vals[8] = {v0.x, v0.y, v0.z, v0.w, v1.x, v1.y, v1.z, v1.w};
#pragma unroll
        for (int mm = 0; mm < 4; mm++) {
            int d  = dseg * 8 + 2 * mm;
            int j0 = d & 63;
            float c0 = g_cos[s_pos * 64 + j0],     sn0 = g_sin[s_pos * 64 + j0];
            float c1 = g_cos[s_pos * 64 + j0 + 1], sn1 = g_sin[s_pos * 64 + j0 + 1];
            float a = vals[2*mm], bb = vals[2*mm+1];
            vals[2*mm]   = (a * c0 - bb * sn0) * scale;
            vals[2*mm+1] = (bb * c1 + a * sn1) * scale;
        }
        uint4 uh, ul;
        split2(vals[0], vals[1], uh.x, ul.x);
        split2(vals[2], vals[3], uh.y, ul.y);
        split2(vals[4], vals[5], uh.z, ul.z);
        split2(vals[6], vals[7], uh.w, ul.w);
        *(uint4*)(sm->qh + r * AQP + dseg * 16) = uh;
        *(uint4*)(sm->ql + r * AQP + dseg * 16) = ul;
    }
    __syncthreads();

    // ---- load Q fragments (persistent in registers) ----
    const uint32_t qbh = smem_u32(sm->qh);
    const uint32_t qbl = smem_u32(sm->ql);
    const uint32_t kbh = smem_u32(sm->kh);
    const uint32_t kbl = smem_u32(sm->kl);
    const uint32_t vbh = smem_u32(sm->vh);
    const uint32_t vbl = smem_u32(sm->vl);
    const uint32_t aoff = (uint32_t)(warp * 16 + (lane & 15)) * AQP + (lane >> 4) * 16;

    uint32_t qfh[8][4], qfl[8][4];
#pragma unroll
    for (int kg = 0; kg < 8; kg++) {
        ldsm_x4(qfh[kg], qbh + aoff + kg * 32);
        ldsm_x4(qfl[kg], qbl + aoff + kg * 32);
    }

    float o[16][4];
#pragma unroll
    for (int i = 0; i < 16; i++)
#pragma unroll
        for (int q = 0; q < 4; q++) o[i][q] = 0.f;
    float m0 = -1e30f, m1 = -1e30f, l0 = 0.f, l1 = 0.f;

    const int g  = lane >> 2;
    const int tg = lane & 3;
    const int gq0 = q0 + warp * 16 + g;
    const int gq1 = gq0 + 8;

    int lo_k = q0 - w + 1; if (lo_k < 0) lo_k = 0;
    const int kc0 = lo_k & ~63;

    for (int kc = kc0; kc <= q0 + 127; kc += 64) {
        __syncthreads();
        // ---- stage K (rope) and V (split only) ----
#pragma unroll
        for (int p = 0; p < 4; p++) {
            int seg = t + p * 256;          // 1024 segs: 64 rows x 16
            int r = seg >> 4, dseg = seg & 15;
            int s_pos = kc + r;
            const float* ksrc = rowbase + (size_t)s_pos * QKV_N + EMB + h * HDIM + dseg * 8;
            float4 v0 = *(const float4*)ksrc;
            float4 v1 = *(const float4*)(ksrc + 4);
            float vals[8] = {v0.x, v0.y, v0.z, v0.w, v1.x, v1.y, v1.z, v1.w};
#pragma unroll
            for (int mm = 0; mm < 4; mm++) {
                int d  = dseg * 8 + 2 * mm;
                int j0 = d & 63;
                float c0 = g_cos[s_pos * 64 + j0],     sn0 = g_sin[s_pos * 64 + j0];
                float c1 = g_cos[s_pos * 64 + j0 + 1], sn1 = g_sin[s_pos * 64 + j0 + 1];
                float a = vals[2*mm], bb = vals[2*mm+1];
                vals[2*mm]   = a * c0 - bb * sn0;
                vals[2*mm+1] = bb * c1 + a * sn1;
            }
            uint4 uh, ul;
            split2(vals[0], vals[1], uh.x, ul.x);
            split2(vals[2], vals[3], uh.y, ul.y);
            split2(vals[4], vals[5], uh.z, ul.z);
            split2(vals[6], vals[7], uh.w, ul.w);
            *(uint4*)(sm->kh + r * AQP + dseg * 16) = uh;
            *(uint4*)(sm->kl + r * AQP + dseg * 16) = ul;

            const float* vsrc = rowbase + (size_t)s_pos * QKV_N + 2 * EMB + h * HDIM + dseg * 8;
            float4 w0 = *(const float4*)vsrc;
            float4 w1 = *(const float4*)(vsrc + 4);
            split2(w0.x, w0.y, uh.x, ul.x);
            split2(w0.z, w0.w, uh.y, ul.y);
            split2(w1.x, w1.y, uh.z, ul.z);
            split2(w1.z, w1.w, uh.w, ul.w);
            *(uint4*)(sm->vh + r * AQP + dseg * 16) = uh;
            *(uint4*)(sm->vl + r * AQP + dseg * 16) = ul;
        }
        __syncthreads();

        // ---- QK^T: s[8][4] over N=64 keys ----
        float s[8][4];
#pragma unroll
        for (int i = 0; i < 8; i++)
#pragma unroll
            for (int q = 0; q < 4; q++) s[i][q] = 0.f;

#pragma unroll
        for (int kg = 0; kg < 8; kg++) {
#pragma unroll
            for (int nf2 = 0; nf2 < 4; nf2++) {
                uint32_t boff = (uint32_t)(nf2 * 16 + ((lane >> 4) & 1) * 8 + (lane & 7)) * AQP
                              + ((lane >> 3) & 1) * 16 + kg * 32;
                uint32_t bh[4], bl[4];
                ldsm_x4(bh, kbh + boff);
                ldsm_x4(bl, kbl + boff);
#pragma unroll
                for (int jj = 0; jj < 2; jj++) {
                    mma16816(s[nf2*2+jj], qfh[kg], bh[2*jj], bh[2*jj+1]);
                    mma16816(s[nf2*2+jj], qfh[kg], bl[2*jj], bl[2*jj+1]);
                    mma16816(s[nf2*2+jj], qfl[kg], bh[2*jj], bh[2*jj+1]);
                }
            }
        }

        // ---- masked online softmax (rows g and g+8) ----
        float mn0 = m0, mn1 = m1;
#pragma unroll
        for (int nf = 0; nf < 8; nf++) {
            int gk0 = kc + nf * 8 + tg * 2;
            int gk1 = gk0 + 1;
            bool k00 = (gk0 <= gq0) && (gk0 > gq0 - w);
            bool k01 = (gk1 <= gq0) && (gk1 > gq0 - w);
            bool k10 = (gk0 <= gq1) && (gk0 > gq1 - w);
            bool k11 = (gk1 <= gq1) && (gk1 > gq1 - w);
            mn0 = fmaxf(mn0, k00 ? s[nf][0] : -1e30f);
            mn0 = fmaxf(mn0, k01 ? s[nf][1] : -1e30f);
            mn1 = fmaxf(mn1, k10 ? s[nf][2] : -1e30f);
            mn1 = fmaxf(mn1, k11 ? s[nf][3] : -1e30f);
        }
        mn0 = fmaxf(mn0, __shfl_xor_sync(0xFFFFFFFFu, mn0, 1));
        mn0 = fmaxf(mn0, __shfl_xor_sync(0xFFFFFFFFu, mn0, 2));
        mn1 = fmaxf(mn1, __shfl_xor_sync(0xFFFFFFFFu, mn1, 1));
        mn1 = fmaxf(mn1, __shfl_xor_sync(0xFFFFFFFFu, mn1, 2));
        float sc0 = __expf(m0 - mn0);
        float sc1 = __expf(m1 - mn1);
        float ls0 = 0.f, ls1 = 0.f;
#pragma unroll
        for (int nf = 0; nf < 8; nf++) {
            int gk0 = kc + nf * 8 + tg * 2;
            int gk1 = gk0 + 1;
            bool k00 = (gk0 <= gq0) && (gk0 > gq0 - w);
            bool k01 = (gk1 <= gq0) && (gk1 > gq0 - w);
            bool k10 = (gk0 <= gq1) && (gk0 > gq1 - w);
            bool k11 = (gk1 <= gq1) && (gk1 > gq1 - w);
            float p00 = k00 ? __expf(s[nf][0] - mn0) : 0.f;
            float p01 = k01 ? __expf(s[nf][1] - mn0) : 0.f;
            float p10 = k10 ? __expf(s[nf][2] - mn1) : 0.f;
            float p11 = k11 ? __expf(s[nf][3] - mn1) : 0.f;
            s[nf][0] = p00; s[nf][1] = p01; s[nf][2] = p10; s[nf][3] = p11;
            ls0 += p00 + p01;
            ls1 += p10 + p11;
        }
        ls0 += __shfl_xor_sync(0xFFFFFFFFu, ls0, 1);
        ls0 += __shfl_xor_sync(0xFFFFFFFFu, ls0, 2);
        ls1 += __shfl_xor_sync(0xFFFFFFFFu, ls1, 1);
        ls1 += __shfl_xor_sync(0xFFFFFFFFu, ls1, 2);
        l0 = l0 * sc0 + ls0;
        l1 = l1 * sc1 + ls1;
        m0 = mn0; m1 = mn1;

#pragma unroll
        for (int i = 0; i < 16; i++) {
            o[i][0] *= sc0; o[i][1] *= sc0;
            o[i][2] *= sc1; o[i][3] *= sc1;
        }

        // ---- PV: P fragments from registers, V via ldmatrix.trans ----
#pragma unroll
        for (int kg2 = 0; kg2 < 4; kg2++) {
            uint32_t ah[4], al[4];
            split2(s[2*kg2][0],   s[2*kg2][1],   ah[0], al[0]);
            split2(s[2*kg2][2],   s[2*kg2][3],   ah[1], al[1]);
            split2(s[2*kg2+1][0], s[2*kg2+1][1], ah[2], al[2]);
            split2(s[2*kg2+1][2], s[2*kg2+1][3], ah[3], al[3]);
#pragma unroll
            for (int nf16 = 0; nf16 < 8; nf16++) {
                uint32_t voff = (uint32_t)(kg2 * 16 + ((lane >> 3) & 1) * 8 + (lane & 7)) * AQP
                              + (uint32_t)(nf16 * 16 + (lane >> 4) * 8) * 2;
                uint32_t bvh[4], bvl[4];
                ldsm_x4_t(bvh, vbh + voff);
                ldsm_x4_t(bvl, vbl + voff);
                mma16816(o[2*nf16],   ah, bvh[0], bvh[1]);
                mma16816(o[2*nf16],   ah, bvl[0], bvl[1]);
                mma16816(o[2*nf16],   al, bvh[0], bvh[1]);
                mma16816(o[2*nf16+1], ah, bvh[2], bvh[3]);
                mma16816(o[2*nf16+1], ah, bvl[2], bvl[3]);
                mma16816(o[2*nf16+1], al, bvh[2], bvh[3]);
            }
        }
    }

    // ---- epilogue: normalize, split to bf16 hi/lo, store ----
    float inv0 = 1.f / l0;
    float inv1 = 1.f / l1;
    size_t row0 = (size_t)(b * S_LEN + q0 + warp * 16 + g);
    size_t row1 = row0 + 8;
#pragma unroll
    for (int nf = 0; nf < 16; nf++) {
        int col = h * HDIM + nf * 8 + tg * 2;
        uint32_t hh, ll;
        split2(o[nf][0] * inv0, o[nf][1] * inv0, hh, ll);
        *(uint32_t*)(oh + row0 * EMB + col) = hh;
        *(uint32_t*)(ol + row0 * EMB + col) = ll;
        split2(o[nf][2] * inv1, o[nf][3] * inv1, hh, ll);
        *(uint32_t*)(oh + row1 * EMB + col) = hh;
        *(uint32_t*)(ol + row1 * EMB + col) = ll;
    }
}

// ---------------- launcher ----------------
extern "C" void kernel_launch(void* const* d_in, const int* in_sizes, int n_in,
                              void* d_out, int out_size)
{
    const float* x     = (const float*)d_in[0];
    const float* w_qkv = (const float*)d_in[1];
    const float* w_out = (const float*)d_in[2];
    const float* w_c1  = (const float*)d_in[3];
    const float* w_c2  = (const float*)d_in[4];
    float* out = (float*)d_out;

    static int attr_done = 0;
    if (!attr_done) {
        cudaFuncSetAttribute(attn_mma_kernel, cudaFuncAttributeMaxDynamicSharedMemorySize,
                             (int)sizeof(AttnSm2));
        cudaFuncSetAttribute(gemm_hmma, cudaFuncAttributeMaxDynamicSharedMemorySize,
                             GEMM_SMEM);
        attr_done = 1;
    }

    void* qkvp = 0; cudaGetSymbolAddress(&qkvp, g_qkv);
    void* ahp  = 0; cudaGetSymbolAddress(&ahp,  g_ah);
    void* alp  = 0; cudaGetSymbolAddress(&alp,  g_al);
    void* bhp  = 0; cudaGetSymbolAddress(&bhp,  g_bh);
    void* blp  = 0; cudaGetSymbolAddress(&blp,  g_bl);

    __nv_bfloat16* ah = (__nv_bfloat16*)ahp;
    __nv_bfloat16* al = (__nv_bfloat16*)alp;
    __nv_bfloat16* bh = (__nv_bfloat16*)bhp;
    __nv_bfloat16* bl = (__nv_bfloat16*)blp;

    rope_table_kernel<<<512, 256>>>();
    stats_kernel<<<dim3(8, 8, 2), 256>>>(x);
    window_kernel<<<1, 512>>>(w_c1, w_c2);

    // GEMM1: qkv = x @ w_qkv^T
    split_kernel<<<(MROWS * EMB / 4 + 255) / 256, 256>>>(x, ah, al, MROWS * EMB / 4);
    split_kernel<<<(QKV_N * EMB / 4 + 255) / 256, 256>>>(w_qkv, bh, bl, QKV_N * EMB / 4);
    gemm_hmma<<<dim3(QKV_N / 128, MROWS / 128), 256, GEMM_SMEM>>>(
        ah, al, bh, bl, (float*)qkvp, QKV_N, EMB);

    // attention (rope fused into Q/K staging), writes bf16 split into ah/al
    attn_mma_kernel<<<dim3(S_LEN / 128, HEADS, B_SZ), 256, sizeof(AttnSm2)>>>(ah, al);

    // GEMM2: out = attn @ w_out^T
    split_kernel<<<(EMB * EMB / 4 + 255) / 256, 256>>>(w_out, bh, bl, EMB * EMB / 4);
    gemm_hmma<<<dim3(EMB / 128, MROWS / 128), 256, GEMM_SMEM>>>(
        ah, al, bh, bl, out, EMB, EMB);
}